// round 4
// baseline (speedup 1.0000x reference)
#include <cuda_runtime.h>
#include <cuda_bf16.h>
#include <math.h>

#define BT    256
#define NCOLS 5000
#define NVEC  1250      // NCOLS/4
#define NVPAD 1280      // ceil to multiple of BT (uniform warp trips for ballot)
#define TOPK  10
#define MAXB  8192
#define CAP   128

__device__ float        g_row[MAXB];
__device__ unsigned int g_ctr = 0;

// Order-preserving float<->uint bijection: f1<f2  <=>  ordf(f1)<ordf(f2)
__device__ __forceinline__ unsigned int ordf(float f) {
    unsigned int u = __float_as_uint(f);
    return (u & 0x80000000u) ? ~u : (u | 0x80000000u);
}
__device__ __forceinline__ float iordf(unsigned int o) {
    unsigned int u = (o & 0x80000000u) ? (o & 0x7fffffffu) : ~o;
    return __uint_as_float(u);
}

// Combined block reduce: sum(int), max(float), max(float)
__device__ __forceinline__ void blockReduceNMM(int& nv, float& my, float& mu,
                                               int* sci, float* scf) {
    int lane = threadIdx.x & 31, w = threadIdx.x >> 5;
    int n = nv; float a = my, b = mu;
#pragma unroll
    for (int o = 16; o; o >>= 1) {
        n += __shfl_down_sync(0xffffffffu, n, o);
        a = fmaxf(a, __shfl_down_sync(0xffffffffu, a, o));
        b = fmaxf(b, __shfl_down_sync(0xffffffffu, b, o));
    }
    if (lane == 0) { sci[w] = n; scf[w] = a; scf[8 + w] = b; }
    __syncthreads();
    if (w == 0) {
        int nn = lane < 8 ? sci[lane] : 0;
        float aa = lane < 8 ? scf[lane] : -INFINITY;
        float bb = lane < 8 ? scf[8 + lane] : -INFINITY;
#pragma unroll
        for (int o = 4; o; o >>= 1) {
            nn += __shfl_down_sync(0xffffffffu, nn, o);
            aa = fmaxf(aa, __shfl_down_sync(0xffffffffu, aa, o));
            bb = fmaxf(bb, __shfl_down_sync(0xffffffffu, bb, o));
        }
        if (lane == 0) { sci[0] = nn; scf[0] = aa; scf[8] = bb; }
    }
    __syncthreads();
    nv = sci[0]; my = scf[0]; mu = scf[8];
    __syncthreads();
}

// Fused block reduce: 8 float sums at once (one barrier pair for everything).
__device__ __forceinline__ void blockReduce8F(float v[8], float* scf /*64*/) {
    int lane = threadIdx.x & 31, w = threadIdx.x >> 5;
#pragma unroll
    for (int o = 16; o; o >>= 1) {
#pragma unroll
        for (int j = 0; j < 8; j++)
            v[j] += __shfl_down_sync(0xffffffffu, v[j], o);
    }
    if (lane == 0) {
#pragma unroll
        for (int j = 0; j < 8; j++) scf[j * 8 + w] = v[j];
    }
    __syncthreads();
    if (w == 0) {
        float x[8];
#pragma unroll
        for (int j = 0; j < 8; j++) x[j] = lane < 8 ? scf[j * 8 + lane] : 0.0f;
#pragma unroll
        for (int o = 4; o; o >>= 1) {
#pragma unroll
            for (int j = 0; j < 8; j++)
                x[j] += __shfl_down_sync(0xffffffffu, x[j], o);
        }
        if (lane == 0) {
#pragma unroll
            for (int j = 0; j < 8; j++) scf[j * 8] = x[j];
        }
    }
    __syncthreads();
#pragma unroll
    for (int j = 0; j < 8; j++) v[j] = scf[j * 8];
    __syncthreads();
}

// In-place inclusive prefix scan of a 256-int shared array (BT==256 threads).
__device__ __forceinline__ void scan256(int* h, int* wtot) {
    int tid = threadIdx.x, lane = tid & 31, w = tid >> 5;
    int v = h[tid];
#pragma unroll
    for (int o = 1; o < 32; o <<= 1) {
        int t = __shfl_up_sync(0xffffffffu, v, o);
        if (lane >= o) v += t;
    }
    if (lane == 31) wtot[w] = v;
    __syncthreads();
    if (w == 0 && lane < 8) {
        int x = wtot[lane];
#pragma unroll
        for (int o = 1; o < 8; o <<= 1) {
            int t = __shfl_up_sync(0xffu, x, o);
            if (lane >= o) x += t;
        }
        wtot[lane] = x;
    }
    __syncthreads();
    h[tid] = v + (w ? wtot[w - 1] : 0);
    __syncthreads();
}

__global__ void __launch_bounds__(BT, 6)
row_kernel(const float* __restrict__ up, const float* __restrict__ dn,
           const float* __restrict__ yt, const int* __restrict__ mk,
           float* __restrict__ out)
{
    __shared__ __align__(16) unsigned int s_oy[NVPAD * 4];   // 20.5 KB
    __shared__ int   s_hist[256];
    __shared__ unsigned long long s_ckU[CAP];
    __shared__ float s_cuU[CAP];
    __shared__ unsigned long long s_ckD[CAP];
    __shared__ int   s_cnt[2];
    __shared__ int   s_misc[4];   // 0:bU 1:rU 2:bD 3:rD
    __shared__ float s_scf[64];
    __shared__ int   s_sci[8];
    __shared__ int   s_wt[8];
    __shared__ unsigned long long s_thr[2];
    __shared__ float s_bsumU;
    __shared__ unsigned int s_last;

    const int row = blockIdx.x, tid = threadIdx.x;
    const int lane = tid & 31, w = tid >> 5;
    const size_t base = (size_t)row * NCOLS;
    const float* upr = up + base;
    const float* dnr = dn + base;

    s_hist[tid] = 0;
    if (tid < 2) s_cnt[tid] = 0;
    __syncthreads();

    // ---------- P1: vectorized load + ordf stage + count/max + L1 histogram ---
    const float4* y4 = (const float4*)(yt + base);
    const float4* u4 = (const float4*)(upr);
    const int4*   m4 = (const int4*)(mk + base);

    int nv = 0; float m_y = -INFINITY, m_up = -INFINITY;

#define P1ELEM(YV, UV, MV, IDX) do {                                         \
        bool v_ = (MV) > 0;                                                  \
        unsigned int o_ = v_ ? ordf(YV) : 0u;                                \
        s_oy[IDX] = o_;                                                      \
        if (v_) { nv++; m_y = fmaxf(m_y, (YV)); m_up = fmaxf(m_up, (UV)); }  \
        unsigned int act_ = __ballot_sync(0xffffffffu, v_);                  \
        if (v_) {                                                            \
            unsigned int bin_ = o_ >> 24;                                    \
            unsigned int mm_ = __match_any_sync(act_, bin_);                 \
            if ((mm_ & ((1u << lane) - 1u)) == 0u)                           \
                atomicAdd(&s_hist[bin_], (int)__popc(mm_));                  \
        }                                                                    \
    } while (0)

#pragma unroll
    for (int i = tid; i < NVPAD; i += BT) {      // 5 uniform trips
        bool inb = i < NVEC;
        float4 yv = make_float4(0.f, 0.f, 0.f, 0.f);
        float4 uv = yv;
        int4   mv = make_int4(0, 0, 0, 0);
        if (inb) { yv = y4[i]; uv = u4[i]; mv = m4[i]; }
        int idx = i * 4;
        P1ELEM(yv.x, uv.x, mv.x, idx + 0);
        P1ELEM(yv.y, uv.y, mv.y, idx + 1);
        P1ELEM(yv.z, uv.z, mv.z, idx + 2);
        P1ELEM(yv.w, uv.w, mv.w, idx + 3);
    }
    __syncthreads();

    blockReduceNMM(nv, m_y, m_up, s_sci, s_scf);

    float loss = 0.0f;
    if (nv > 0) {
        const int k = nv < TOPK ? nv : TOPK;

        // ---------- level-1 bin pick, both ends from one histogram -----------
        scan256(s_hist, s_wt);
        {
            int pref = s_hist[tid];
            int cnt  = pref - (tid ? s_hist[tid - 1] : 0);
            if (cnt > 0) {
                int S = nv - pref;                     // strictly above this bin
                if (S < k && S + cnt >= k) { s_misc[0] = tid; s_misc[1] = k - S; }
                int below = pref - cnt;                // strictly below this bin
                if (below < k && pref >= k) { s_misc[2] = tid; s_misc[3] = k - below; }
            }
        }
        __syncthreads();
        const int bU = s_misc[0], rU = s_misc[1];
        const int bD = s_misc[2], rD = s_misc[3];

        // ---------- P2: sum-exp + KL acc + softplus(up) + boundary compaction -
        float syl = 0.f, sul = 0.f, kac = 0.f, bub = 0.f, usel = 0.f;
        for (int i = tid; i < NCOLS; i += BT) {
            unsigned int o = s_oy[i];
            if (!o) continue;
            float y = iordf(o);
            float u = upr[i];
            float ey = __expf(y - m_y);
            float eu = __expf(u - m_up);
            syl += ey; sul += eu; kac += ey * (y - u);
            bub += fmaxf(u, 0.f) + __logf(1.f + __expf(-fabsf(u)));
            int b1 = (int)(o >> 24);
            if (b1 > bU) usel += u;           // certainly in up top-k
            else if (b1 == bU) {
                int p = atomicAdd(&s_cnt[0], 1);
                if (p < CAP) {
                    s_ckU[p] = ((unsigned long long)o << 32) | (unsigned int)~i;
                    s_cuU[p] = u;
                }
            }
            if (b1 == bD) {
                int p = atomicAdd(&s_cnt[1], 1);
                if (p < CAP)
                    s_ckD[p] = ((unsigned long long)(~o) << 32) | (unsigned int)~i;
            }
        }
        __syncthreads();

        // ---------- selection: warp0 -> up (+ boundary u sum), warp1 -> down --
        if (w == 0) {
            int cnt = s_cnt[0];
            unsigned long long thr = ~0ull;
            float bs = 0.f;
            if (cnt <= CAP) {
                for (int t = 0; t < rU; t++) {
                    unsigned long long lm = 0ull;
                    for (int j = lane; j < cnt; j += 32) {
                        unsigned long long kk = s_ckU[j];
                        if (kk < thr && kk > lm) lm = kk;
                    }
#pragma unroll
                    for (int o = 16; o; o >>= 1) {
                        unsigned long long v = __shfl_down_sync(0xffffffffu, lm, o);
                        if (v > lm) lm = v;
                    }
                    thr = __shfl_sync(0xffffffffu, lm, 0);
                }
                for (int j = lane; j < cnt; j += 32)
                    if (s_ckU[j] >= thr) bs += s_cuU[j];
            } else {   // rare fallback: full scan filtered by bin
                for (int t = 0; t < rU; t++) {
                    unsigned long long lm = 0ull;
                    for (int j = lane; j < NCOLS; j += 32) {
                        unsigned int o = s_oy[j];
                        if (!o || (int)(o >> 24) != bU) continue;
                        unsigned long long kk =
                            ((unsigned long long)o << 32) | (unsigned int)~j;
                        if (kk < thr && kk > lm) lm = kk;
                    }
#pragma unroll
                    for (int o = 16; o; o >>= 1) {
                        unsigned long long v = __shfl_down_sync(0xffffffffu, lm, o);
                        if (v > lm) lm = v;
                    }
                    thr = __shfl_sync(0xffffffffu, lm, 0);
                }
                for (int j = lane; j < NCOLS; j += 32) {
                    unsigned int o = s_oy[j];
                    if (!o || (int)(o >> 24) != bU) continue;
                    unsigned long long kk =
                        ((unsigned long long)o << 32) | (unsigned int)~j;
                    if (kk >= thr) bs += upr[j];
                }
            }
#pragma unroll
            for (int o = 16; o; o >>= 1)
                bs += __shfl_down_sync(0xffffffffu, bs, o);
            if (lane == 0) { s_thr[0] = thr; s_bsumU = bs; }
        } else if (w == 1) {
            int cnt = s_cnt[1];
            unsigned long long thr = ~0ull;
            if (cnt <= CAP) {
                for (int t = 0; t < rD; t++) {
                    unsigned long long lm = 0ull;
                    for (int j = lane; j < cnt; j += 32) {
                        unsigned long long kk = s_ckD[j];
                        if (kk < thr && kk > lm) lm = kk;
                    }
#pragma unroll
                    for (int o = 16; o; o >>= 1) {
                        unsigned long long v = __shfl_down_sync(0xffffffffu, lm, o);
                        if (v > lm) lm = v;
                    }
                    thr = __shfl_sync(0xffffffffu, lm, 0);
                }
            } else {
                for (int t = 0; t < rD; t++) {
                    unsigned long long lm = 0ull;
                    for (int j = lane; j < NCOLS; j += 32) {
                        unsigned int o = s_oy[j];
                        if (!o || (int)(o >> 24) != bD) continue;
                        unsigned long long kk =
                            ((unsigned long long)(~o) << 32) | (unsigned int)~j;
                        if (kk < thr && kk > lm) lm = kk;
                    }
#pragma unroll
                    for (int o = 16; o; o >>= 1) {
                        unsigned long long v = __shfl_down_sync(0xffffffffu, lm, o);
                        if (v > lm) lm = v;
                    }
                    thr = __shfl_sync(0xffffffffu, lm, 0);
                }
            }
            if (lane == 0) s_thr[1] = thr;
        }
        __syncthreads();
        const unsigned long long thrD = s_thr[1];

        // ---------- P4: down path only ----------
        float bdb = 0.f, dsel = 0.f;
        for (int i = tid; i < NCOLS; i += BT) {
            unsigned int o = s_oy[i];
            if (!o) continue;
            float d = dnr[i];
            bdb += fmaxf(d, 0.f) + __logf(1.f + __expf(-fabsf(d)));
            int b1 = (int)(o >> 24);
            if (b1 < bD) dsel += d;
            else if (b1 == bD) {
                unsigned long long kd =
                    ((unsigned long long)(~o) << 32) | (unsigned int)~i;
                if (kd >= thrD) dsel += d;
            }
        }

        // ---------- one fused reduction for everything ----------
        float v[8] = { syl, sul, kac, bub, usel, bdb, dsel, 0.f };
        blockReduce8F(v, s_scf);
        syl = v[0]; sul = v[1]; kac = v[2]; bub = v[3];
        usel = v[4] + s_bsumU; bdb = v[5]; dsel = v[6];

        float bu = bub - usel;
        float bd = bdb - dsel;
        float kl = kac / syl + (m_up + logf(sul)) - (m_y + logf(syl));
        loss = (bu + 0.5f * bd + 0.3f * kl) / (float)nv;
    }

    if (tid == 0) g_row[row] = loss;
    __threadfence();
    if (tid == 0) s_last = (atomicAdd(&g_ctr, 1u) == gridDim.x - 1u);
    __syncthreads();

    // last CTA reduces all rows (deterministic order) and writes scalar
    if (s_last) {
        __threadfence();
        float s = 0.f;
        for (int i = tid; i < (int)gridDim.x; i += BT) s += g_row[i];
        float v[8] = { s, 0.f, 0.f, 0.f, 0.f, 0.f, 0.f, 0.f };
        blockReduce8F(v, s_scf);
        if (tid == 0) { out[0] = v[0] / (float)gridDim.x; g_ctr = 0u; }
    }
}

extern "C" void kernel_launch(void* const* d_in, const int* in_sizes, int n_in,
                              void* d_out, int out_size) {
    const float* up = (const float*)d_in[0];
    const float* dn = (const float*)d_in[1];
    const float* yt = (const float*)d_in[2];
    const int*   mk = (const int*)d_in[3];
    int B = in_sizes[0] / NCOLS;
    if (B > MAXB) B = MAXB;
    row_kernel<<<B, BT>>>(up, dn, yt, mk, (float*)d_out);
}

// round 5
// speedup vs baseline: 1.7087x; 1.7087x over previous
#include <cuda_runtime.h>
#include <cuda_bf16.h>
#include <math.h>

#define BT    256
#define NCOLS 5000
#define NVEC  1250      // NCOLS/4
#define NVPAD 1280      // ceil to multiple of BT (uniform warp trips for ballot)
#define TOPK  10
#define MAXB  8192
#define CAP   512

__device__ float        g_row[MAXB];
__device__ unsigned int g_ctr = 0;

// Order-preserving float<->uint bijection: f1<f2  <=>  ordf(f1)<ordf(f2)
__device__ __forceinline__ unsigned int ordf(float f) {
    unsigned int u = __float_as_uint(f);
    return (u & 0x80000000u) ? ~u : (u | 0x80000000u);
}
__device__ __forceinline__ float iordf(unsigned int o) {
    unsigned int u = (o & 0x80000000u) ? (o & 0x7fffffffu) : ~o;
    return __uint_as_float(u);
}

// Combined block reduce: sum(int), max(float), max(float)
__device__ __forceinline__ void blockReduceNMM(int& nv, float& my, float& mu,
                                               int* sci, float* scf) {
    int lane = threadIdx.x & 31, w = threadIdx.x >> 5;
    int n = nv; float a = my, b = mu;
#pragma unroll
    for (int o = 16; o; o >>= 1) {
        n += __shfl_down_sync(0xffffffffu, n, o);
        a = fmaxf(a, __shfl_down_sync(0xffffffffu, a, o));
        b = fmaxf(b, __shfl_down_sync(0xffffffffu, b, o));
    }
    if (lane == 0) { sci[w] = n; scf[w] = a; scf[8 + w] = b; }
    __syncthreads();
    if (w == 0) {
        int nn = lane < 8 ? sci[lane] : 0;
        float aa = lane < 8 ? scf[lane] : -INFINITY;
        float bb = lane < 8 ? scf[8 + lane] : -INFINITY;
#pragma unroll
        for (int o = 4; o; o >>= 1) {
            nn += __shfl_down_sync(0xffffffffu, nn, o);
            aa = fmaxf(aa, __shfl_down_sync(0xffffffffu, aa, o));
            bb = fmaxf(bb, __shfl_down_sync(0xffffffffu, bb, o));
        }
        if (lane == 0) { sci[0] = nn; scf[0] = aa; scf[8] = bb; }
    }
    __syncthreads();
    nv = sci[0]; my = scf[0]; mu = scf[8];
    __syncthreads();
}

// Fused block reduce: 8 float sums at once.
__device__ __forceinline__ void blockReduce8F(float v[8], float* scf /*64*/) {
    int lane = threadIdx.x & 31, w = threadIdx.x >> 5;
#pragma unroll
    for (int o = 16; o; o >>= 1) {
#pragma unroll
        for (int j = 0; j < 8; j++)
            v[j] += __shfl_down_sync(0xffffffffu, v[j], o);
    }
    if (lane == 0) {
#pragma unroll
        for (int j = 0; j < 8; j++) scf[j * 8 + w] = v[j];
    }
    __syncthreads();
    if (w == 0) {
        float x[8];
#pragma unroll
        for (int j = 0; j < 8; j++) x[j] = lane < 8 ? scf[j * 8 + lane] : 0.0f;
#pragma unroll
        for (int o = 4; o; o >>= 1) {
#pragma unroll
            for (int j = 0; j < 8; j++)
                x[j] += __shfl_down_sync(0xffffffffu, x[j], o);
        }
        if (lane == 0) {
#pragma unroll
            for (int j = 0; j < 8; j++) scf[j * 8] = x[j];
        }
    }
    __syncthreads();
#pragma unroll
    for (int j = 0; j < 8; j++) v[j] = scf[j * 8];
    __syncthreads();
}

// In-place inclusive prefix scan of a 256-int shared array (BT==256 threads).
__device__ __forceinline__ void scan256(int* h, int* wtot) {
    int tid = threadIdx.x, lane = tid & 31, w = tid >> 5;
    int v = h[tid];
#pragma unroll
    for (int o = 1; o < 32; o <<= 1) {
        int t = __shfl_up_sync(0xffffffffu, v, o);
        if (lane >= o) v += t;
    }
    if (lane == 31) wtot[w] = v;
    __syncthreads();
    if (w == 0 && lane < 8) {
        int x = wtot[lane];
#pragma unroll
        for (int o = 1; o < 8; o <<= 1) {
            int t = __shfl_up_sync(0xffu, x, o);
            if (lane >= o) x += t;
        }
        wtot[lane] = x;
    }
    __syncthreads();
    h[tid] = v + (w ? wtot[w - 1] : 0);
    __syncthreads();
}

// Dual scan: two 256-int arrays at once.
__device__ __forceinline__ void scan256dual(int* ha, int* hb, int* wta, int* wtb) {
    int tid = threadIdx.x, lane = tid & 31, w = tid >> 5;
    int va = ha[tid], vb = hb[tid];
#pragma unroll
    for (int o = 1; o < 32; o <<= 1) {
        int ta = __shfl_up_sync(0xffffffffu, va, o);
        int tb = __shfl_up_sync(0xffffffffu, vb, o);
        if (lane >= o) { va += ta; vb += tb; }
    }
    if (lane == 31) { wta[w] = va; wtb[w] = vb; }
    __syncthreads();
    if (w == 0 && lane < 8) {
        int xa = wta[lane], xb = wtb[lane];
#pragma unroll
        for (int o = 1; o < 8; o <<= 1) {
            int ta = __shfl_up_sync(0xffu, xa, o);
            int tb = __shfl_up_sync(0xffu, xb, o);
            if (lane >= o) { xa += ta; xb += tb; }
        }
        wta[lane] = xa; wtb[lane] = xb;
    }
    __syncthreads();
    ha[tid] = va + (w ? wta[w - 1] : 0);
    hb[tid] = vb + (w ? wtb[w - 1] : 0);
    __syncthreads();
}

// warp max of u64 + broadcast
__device__ __forceinline__ unsigned long long warpMaxBcast(unsigned long long lm) {
#pragma unroll
    for (int o = 16; o; o >>= 1) {
        unsigned long long v = __shfl_down_sync(0xffffffffu, lm, o);
        if (v > lm) lm = v;
    }
    return __shfl_sync(0xffffffffu, lm, 0);
}

__global__ void __launch_bounds__(BT, 5)
row_kernel(const float* __restrict__ up, const float* __restrict__ dn,
           const float* __restrict__ yt, const int* __restrict__ mk,
           float* __restrict__ out)
{
    __shared__ __align__(16) unsigned int s_oy[NVPAD * 4];   // 20.5 KB
    __shared__ int   s_hist[256];
    __shared__ int   s_histU[256];
    __shared__ int   s_histD[256];
    __shared__ unsigned long long s_ckU[CAP];
    __shared__ float s_cuU[CAP];
    __shared__ unsigned long long s_ckD[CAP];
    __shared__ float s_cdD[CAP];
    __shared__ int   s_cnt[2];
    __shared__ int   s_misc[8];   // 0:bU 1:rU 2:bD 3:rD 4:t2U 5:r2U 6:t2D 7:r2D
    __shared__ float s_scf[64];
    __shared__ int   s_sci[8];
    __shared__ int   s_wt[16];
    __shared__ float s_bs[2];
    __shared__ unsigned int s_last;

    const int row = blockIdx.x, tid = threadIdx.x;
    const int lane = tid & 31, w = tid >> 5;
    const size_t base = (size_t)row * NCOLS;
    const float* upr = up + base;
    const float* dnr = dn + base;

    s_hist[tid] = 0; s_histU[tid] = 0; s_histD[tid] = 0;
    if (tid < 2) s_cnt[tid] = 0;
    __syncthreads();

    // ---------- P1: vectorized load + ordf stage + count/max + L1 histogram ---
    const float4* y4 = (const float4*)(yt + base);
    const float4* u4 = (const float4*)(upr);
    const int4*   m4 = (const int4*)(mk + base);

    int nv = 0; float m_y = -INFINITY, m_up = -INFINITY;

#define P1ELEM(YV, UV, MV, OUT) do {                                         \
        bool v_ = (MV) > 0;                                                  \
        unsigned int o_ = v_ ? ordf(YV) : 0u;                                \
        (OUT) = o_;                                                          \
        if (v_) { nv++; m_y = fmaxf(m_y, (YV)); m_up = fmaxf(m_up, (UV)); }  \
        unsigned int act_ = __ballot_sync(0xffffffffu, v_);                  \
        if (v_) {                                                            \
            unsigned int bin_ = o_ >> 24;                                    \
            unsigned int mm_ = __match_any_sync(act_, bin_);                 \
            if ((mm_ & ((1u << lane) - 1u)) == 0u)                           \
                atomicAdd(&s_hist[bin_], (int)__popc(mm_));                  \
        }                                                                    \
    } while (0)

#pragma unroll
    for (int i = tid; i < NVPAD; i += BT) {      // 5 uniform trips
        bool inb = i < NVEC;
        float4 yv = make_float4(0.f, 0.f, 0.f, 0.f);
        float4 uv = yv;
        int4   mv = make_int4(0, 0, 0, 0);
        if (inb) { yv = y4[i]; uv = u4[i]; mv = m4[i]; }
        uint4 ov;
        P1ELEM(yv.x, uv.x, mv.x, ov.x);
        P1ELEM(yv.y, uv.y, mv.y, ov.y);
        P1ELEM(yv.z, uv.z, mv.z, ov.z);
        P1ELEM(yv.w, uv.w, mv.w, ov.w);
        ((uint4*)s_oy)[i] = ov;
    }
    __syncthreads();

    blockReduceNMM(nv, m_y, m_up, s_sci, s_scf);

    float loss = 0.0f;
    if (nv > 0) {
        const int k = nv < TOPK ? nv : TOPK;

        // ---------- level-1 bin pick, both ends from one histogram -----------
        scan256(s_hist, s_wt);
        {
            int pref = s_hist[tid];
            int cnt  = pref - (tid ? s_hist[tid - 1] : 0);
            if (cnt > 0) {
                int S = nv - pref;                     // strictly above this bin
                if (S < k && S + cnt >= k) { s_misc[0] = tid; s_misc[1] = k - S; }
                int below = pref - cnt;                // strictly below this bin
                if (below < k && pref >= k) { s_misc[2] = tid; s_misc[3] = k - below; }
            }
        }
        __syncthreads();
        const int bU = s_misc[0], rU = s_misc[1];
        const int bD = s_misc[2], rD = s_misc[3];

        // ---------- P2: everything per-element, one vectorized scan ----------
        float syl = 0.f, sul = 0.f, kac = 0.f, bub = 0.f, bdb = 0.f;
        float usel = 0.f, dsel = 0.f;
        const float4* d4 = (const float4*)(dnr);

#define P2ELEM(OV, UV, DV, IDX) do {                                          \
        unsigned int o_ = (OV);                                               \
        if (o_) {                                                             \
            float y_ = iordf(o_);                                             \
            float u_ = (UV), d_ = (DV);                                       \
            float ey_ = __expf(y_ - m_y);                                     \
            syl += ey_; kac += ey_ * (y_ - u_);                               \
            sul += __expf(u_ - m_up);                                         \
            bub += fmaxf(u_, 0.f) + __logf(1.f + __expf(-fabsf(u_)));         \
            bdb += fmaxf(d_, 0.f) + __logf(1.f + __expf(-fabsf(d_)));         \
            int b1_ = (int)(o_ >> 24);                                        \
            if (b1_ > bU) usel += u_;                                         \
            else if (b1_ == bU) {                                             \
                int p_ = atomicAdd(&s_cnt[0], 1);                             \
                if (p_ < CAP) {                                               \
                    s_ckU[p_] = ((unsigned long long)o_ << 32)                \
                                | (unsigned int)~(IDX);                       \
                    s_cuU[p_] = u_;                                           \
                }                                                             \
            }                                                                 \
            if (b1_ < bD) dsel += d_;                                         \
            else if (b1_ == bD) {                                             \
                int p_ = atomicAdd(&s_cnt[1], 1);                             \
                if (p_ < CAP) {                                               \
                    s_ckD[p_] = ((unsigned long long)(~o_) << 32)             \
                                | (unsigned int)~(IDX);                       \
                    s_cdD[p_] = d_;                                           \
                }                                                             \
            }                                                                 \
        }                                                                     \
    } while (0)

        for (int i = tid; i < NVEC; i += BT) {
            uint4  ov = ((const uint4*)s_oy)[i];
            float4 uv = u4[i];
            float4 dv = d4[i];
            int idx = i * 4;
            P2ELEM(ov.x, uv.x, dv.x, idx + 0);
            P2ELEM(ov.y, uv.y, dv.y, idx + 1);
            P2ELEM(ov.z, uv.z, dv.z, idx + 2);
            P2ELEM(ov.w, uv.w, dv.w, idx + 3);
        }
        __syncthreads();

        const int cntU = s_cnt[0], cntD = s_cnt[1];
        const bool okU = cntU <= CAP, okD = cntD <= CAP;

        // candidate histograms over (key>>48)&255 (next 8 ordered bits)
        if (okU)
            for (int j = tid; j < cntU; j += BT)
                atomicAdd(&s_histU[(int)((s_ckU[j] >> 48) & 255u)], 1);
        if (okD)
            for (int j = tid; j < cntD; j += BT)
                atomicAdd(&s_histD[(int)((s_ckD[j] >> 48) & 255u)], 1);

        // fused reduction (its barriers also fence the histogram atomics)
        float v[8] = { syl, sul, kac, bub, bdb, usel, dsel, 0.f };
        blockReduce8F(v, s_scf);
        syl = v[0]; sul = v[1]; kac = v[2]; bub = v[3]; bdb = v[4];
        usel = v[5]; dsel = v[6];

        // ---------- level-2 pick over candidates ----------
        scan256dual(s_histU, s_histD, s_wt, s_wt + 8);
        {
            if (okU) {
                int pref = s_histU[tid];
                int cnt  = pref - (tid ? s_histU[tid - 1] : 0);
                int tot  = s_histU[255];
                if (cnt > 0) {
                    int S = tot - pref;
                    if (S < rU && S + cnt >= rU) { s_misc[4] = tid; s_misc[5] = rU - S; }
                }
            }
            if (okD) {
                int pref = s_histD[tid];
                int cnt  = pref - (tid ? s_histD[tid - 1] : 0);
                int tot  = s_histD[255];
                if (cnt > 0) {
                    int S = tot - pref;
                    if (S < rD && S + cnt >= rD) { s_misc[6] = tid; s_misc[7] = rD - S; }
                }
            }
        }
        __syncthreads();

        // ---------- exact thresholds + boundary sums: warp0 up, warp1 down ----
        if (w == 0) {
            float bs = 0.f;
            if (okU) {
                int t2 = s_misc[4], r2 = s_misc[5];
                unsigned long long thr = ~0ull;
                for (int t = 0; t < r2; t++) {
                    unsigned long long lm = 0ull;
                    for (int j = lane; j < cntU; j += 32) {
                        unsigned long long kk = s_ckU[j];
                        if ((int)((kk >> 48) & 255u) == t2 && kk < thr && kk > lm)
                            lm = kk;
                    }
                    thr = warpMaxBcast(lm);
                }
                for (int j = lane; j < cntU; j += 32)
                    if (s_ckU[j] >= thr) bs += s_cuU[j];
            } else {   // overflow fallback (not expected): full-array selection
                unsigned long long thr = ~0ull;
                for (int t = 0; t < rU; t++) {
                    unsigned long long lm = 0ull;
                    for (int j = lane; j < NCOLS; j += 32) {
                        unsigned int o = s_oy[j];
                        if (!o || (int)(o >> 24) != bU) continue;
                        unsigned long long kk =
                            ((unsigned long long)o << 32) | (unsigned int)~j;
                        if (kk < thr && kk > lm) lm = kk;
                    }
                    thr = warpMaxBcast(lm);
                }
                for (int j = lane; j < NCOLS; j += 32) {
                    unsigned int o = s_oy[j];
                    if (!o || (int)(o >> 24) != bU) continue;
                    unsigned long long kk =
                        ((unsigned long long)o << 32) | (unsigned int)~j;
                    if (kk >= thr) bs += upr[j];
                }
            }
#pragma unroll
            for (int o = 16; o; o >>= 1)
                bs += __shfl_down_sync(0xffffffffu, bs, o);
            if (lane == 0) s_bs[0] = bs;
        } else if (w == 1) {
            float bs = 0.f;
            if (okD) {
                int t2 = s_misc[6], r2 = s_misc[7];
                unsigned long long thr = ~0ull;
                for (int t = 0; t < r2; t++) {
                    unsigned long long lm = 0ull;
                    for (int j = lane; j < cntD; j += 32) {
                        unsigned long long kk = s_ckD[j];
                        if ((int)((kk >> 48) & 255u) == t2 && kk < thr && kk > lm)
                            lm = kk;
                    }
                    thr = warpMaxBcast(lm);
                }
                for (int j = lane; j < cntD; j += 32)
                    if (s_ckD[j] >= thr) bs += s_cdD[j];
            } else {
                unsigned long long thr = ~0ull;
                for (int t = 0; t < rD; t++) {
                    unsigned long long lm = 0ull;
                    for (int j = lane; j < NCOLS; j += 32) {
                        unsigned int o = s_oy[j];
                        if (!o || (int)(o >> 24) != bD) continue;
                        unsigned long long kk =
                            ((unsigned long long)(~o) << 32) | (unsigned int)~j;
                        if (kk < thr && kk > lm) lm = kk;
                    }
                    thr = warpMaxBcast(lm);
                }
                for (int j = lane; j < NCOLS; j += 32) {
                    unsigned int o = s_oy[j];
                    if (!o || (int)(o >> 24) != bD) continue;
                    unsigned long long kk =
                        ((unsigned long long)(~o) << 32) | (unsigned int)~j;
                    if (kk >= thr) bs += dnr[j];
                }
            }
#pragma unroll
            for (int o = 16; o; o >>= 1)
                bs += __shfl_down_sync(0xffffffffu, bs, o);
            if (lane == 0) s_bs[1] = bs;
        }
        __syncthreads();

        float bu = bub - (usel + s_bs[0]);
        float bd = bdb - (dsel + s_bs[1]);
        float kl = kac / syl + (m_up + logf(sul)) - (m_y + logf(syl));
        loss = (bu + 0.5f * bd + 0.3f * kl) / (float)nv;
    }

    if (tid == 0) g_row[row] = loss;
    __threadfence();
    if (tid == 0) s_last = (atomicAdd(&g_ctr, 1u) == gridDim.x - 1u);
    __syncthreads();

    // last CTA reduces all rows (deterministic order) and writes scalar
    if (s_last) {
        __threadfence();
        float s = 0.f;
        for (int i = tid; i < (int)gridDim.x; i += BT) s += g_row[i];
        float v[8] = { s, 0.f, 0.f, 0.f, 0.f, 0.f, 0.f, 0.f };
        blockReduce8F(v, s_scf);
        if (tid == 0) { out[0] = v[0] / (float)gridDim.x; g_ctr = 0u; }
    }
}

extern "C" void kernel_launch(void* const* d_in, const int* in_sizes, int n_in,
                              void* d_out, int out_size) {
    const float* up = (const float*)d_in[0];
    const float* dn = (const float*)d_in[1];
    const float* yt = (const float*)d_in[2];
    const int*   mk = (const int*)d_in[3];
    int B = in_sizes[0] / NCOLS;
    if (B > MAXB) B = MAXB;
    row_kernel<<<B, BT>>>(up, dn, yt, mk, (float*)d_out);
}